// round 2
// baseline (speedup 1.0000x reference)
#include <cuda_runtime.h>
#include <cuda_bf16.h>
#include <math.h>

#define N_NODES 100000
#define D_IN    64
#define D_H     32
#define E_EDGES 1600000

// ---------------- scratch (device globals) ----------------------------------
__device__ float g_ycp [N_NODES * D_H];   // x_customer @ W1l_r1
__device__ float g_ypc [N_NODES * D_H];   // x_product  @ W1l_r2
__device__ int   g_off_p[N_NODES + 1];    // CSR offsets, dst=product (c2p)
__device__ int   g_off_c[N_NODES + 1];    // CSR offsets, dst=customer (p2c)
__device__ int   g_cur_p[N_NODES];        // fill cursors / counts
__device__ int   g_cur_c[N_NODES];
__device__ int   g_adj_p[E_EDGES];        // neighbor lists (src ids)
__device__ int   g_adj_c[E_EDGES];
__device__ float g_gc  [N_NODES];         // per-customer folded scalar
__device__ float g_w2l_eff[D_H];
__device__ float g_w2r_eff[D_H];
__device__ float g_bias_eff[1];

// ---------------- kernels ---------------------------------------------------

__global__ void k_zero_i(int* __restrict__ p, int n) {
    int i = blockIdx.x * blockDim.x + threadIdx.x;
    if (i < n) p[i] = 0;
}

// Effective layer2+head weights: w_eff[i] = sum_j W2[i][j] * Wlin[j]
__global__ void k_eff(const float* __restrict__ W2l, const float* __restrict__ W2r,
                      const float* __restrict__ b2, const float* __restrict__ Wlin,
                      const float* __restrict__ blin) {
    int i = threadIdx.x;  // 0..31
    float wl = 0.f, wr = 0.f;
    #pragma unroll
    for (int j = 0; j < D_H; ++j) {
        float wj = Wlin[j];
        wl += W2l[i * D_H + j] * wj;
        wr += W2r[i * D_H + j] * wj;
    }
    g_w2l_eff[i] = wl;
    g_w2r_eff[i] = wr;
    float bv = b2[i] * Wlin[i];
    #pragma unroll
    for (int o = 16; o; o >>= 1) bv += __shfl_xor_sync(0xffffffffu, bv, o);
    if (i == 0) g_bias_eff[0] = bv + blin[0];
}

// y[n,32] = x[n,64] @ W[64,32]. 8 nodes per 256-thread block.
__global__ void k_proj(const float* __restrict__ x, const float* __restrict__ W,
                       float* __restrict__ y, int n) {
    __shared__ float sW[D_IN * D_H];
    __shared__ float sx[8][D_IN];
    int tid = threadIdx.x;
    for (int i = tid; i < D_IN * D_H; i += 256) sW[i] = W[i];
    int nodeBase = blockIdx.x * 8;
    for (int i = tid; i < 8 * D_IN; i += 256) {
        int node = nodeBase + (i >> 6);
        sx[i >> 6][i & 63] = (node < n) ? x[(size_t)node * D_IN + (i & 63)] : 0.f;
    }
    __syncthreads();
    int local = tid >> 5, j = tid & 31;
    int node = nodeBase + local;
    if (node >= n) return;
    float acc = 0.f;
    #pragma unroll
    for (int k = 0; k < D_IN; ++k) acc += sx[local][k] * sW[k * D_H + j];
    y[(size_t)node * D_H + j] = acc;
}

// degree count: cnt[dst]++
__global__ void k_count(const int* __restrict__ edge, int* __restrict__ cnt, int E) {
    int e = blockIdx.x * blockDim.x + threadIdx.x;
    if (e >= E) return;
    atomicAdd(cnt + __ldg(&edge[E + e]), 1);
}

// single-block exclusive scan over cnt[n] -> off[n+1], cur[n]=off[i]
__global__ void k_scan(const int* __restrict__ cnt, int* __restrict__ off,
                       int* __restrict__ cur, int n) {
    __shared__ int ssum[1024];
    int t = threadIdx.x;
    int chunk = (n + 1023) >> 10;
    int lo = t * chunk, hi = min(lo + chunk, n);
    int s = 0;
    for (int i = lo; i < hi; ++i) s += cnt[i];
    ssum[t] = s;
    __syncthreads();
    for (int d = 1; d < 1024; d <<= 1) {
        int v = (t >= d) ? ssum[t - d] : 0;
        __syncthreads();
        if (t >= d) ssum[t] += v;
        __syncthreads();
    }
    int run = (t == 0) ? 0 : ssum[t - 1];
    for (int i = lo; i < hi; ++i) {
        off[i] = run; cur[i] = run;
        run += cnt[i];
    }
    if (t == 1023) off[n] = ssum[1023];
}

// fill adjacency: adj[cur[dst]++] = src
__global__ void k_fill(const int* __restrict__ edge, int* __restrict__ cur,
                       int* __restrict__ adj, int E) {
    int e = blockIdx.x * blockDim.x + threadIdx.x;
    if (e >= E) return;
    int s = __ldg(&edge[e]);
    int d = __ldg(&edge[E + e]);
    int pos = atomicAdd(cur + d, 1);
    adj[pos] = s;
}

// Customer gather: mean over p2c neighbors of y_pc, + x_c@W1r_r2 + b, relu,
// fold with w2l_eff -> scalar g_c. Warp per node.
__global__ void k_gather_c(const float* __restrict__ x, const float* __restrict__ Wr,
                           const float* __restrict__ b, const float* __restrict__ y,
                           const int* __restrict__ off, const int* __restrict__ adj,
                           const float* __restrict__ weff, float* __restrict__ g, int n) {
    __shared__ float sW[D_IN * D_H];
    for (int i = threadIdx.x; i < D_IN * D_H; i += 256) sW[i] = Wr[i];
    __syncthreads();
    int warp = threadIdx.x >> 5, j = threadIdx.x & 31;
    int node = blockIdx.x * 8 + warp;
    if (node >= n) return;
    int base = off[node], end = off[node + 1];
    int deg = end - base;
    float a0 = 0.f, a1 = 0.f, a2 = 0.f, a3 = 0.f;
    for (int i = base; i < end; i += 32) {
        int nbr = (i + j < end) ? adj[i + j] : 0;
        int m = min(32, end - i);
        int k = 0;
        for (; k + 4 <= m; k += 4) {
            int n0 = __shfl_sync(0xffffffffu, nbr, k);
            int n1 = __shfl_sync(0xffffffffu, nbr, k + 1);
            int n2 = __shfl_sync(0xffffffffu, nbr, k + 2);
            int n3 = __shfl_sync(0xffffffffu, nbr, k + 3);
            a0 += y[(size_t)n0 * D_H + j];
            a1 += y[(size_t)n1 * D_H + j];
            a2 += y[(size_t)n2 * D_H + j];
            a3 += y[(size_t)n3 * D_H + j];
        }
        for (; k < m; ++k) {
            int nk = __shfl_sync(0xffffffffu, nbr, k);
            a0 += y[(size_t)nk * D_H + j];
        }
    }
    float mean = (a0 + a1 + a2 + a3) / fmaxf((float)deg, 1.0f);
    float xa = x[(size_t)node * D_IN + j];
    float xb = x[(size_t)node * D_IN + 32 + j];
    float lin = b[j];
    #pragma unroll
    for (int k = 0; k < 32; ++k)
        lin += __shfl_sync(0xffffffffu, xa, k) * sW[k * D_H + j];
    #pragma unroll
    for (int k = 0; k < 32; ++k)
        lin += __shfl_sync(0xffffffffu, xb, k) * sW[(k + 32) * D_H + j];
    float h = fmaxf(mean + lin, 0.0f);
    float v = h * weff[j];
    #pragma unroll
    for (int o = 16; o; o >>= 1) v += __shfl_xor_sync(0xffffffffu, v, o);
    if (j == 0) g[node] = v;
}

// Product gather: mean over c2p neighbors of y_cp (layer1) AND g_c (layer2),
// h_p = relu(mean1 + x_p@W1r_r1 + b), out = sigmoid(mean_gc + dot(h_p,w2r_eff) + bias).
__global__ void k_gather_p(const float* __restrict__ x, const float* __restrict__ Wr,
                           const float* __restrict__ b, const float* __restrict__ y,
                           const int* __restrict__ off, const int* __restrict__ adj,
                           const float* __restrict__ weff, const float* __restrict__ gc,
                           float* __restrict__ out, int n) {
    __shared__ float sW[D_IN * D_H];
    for (int i = threadIdx.x; i < D_IN * D_H; i += 256) sW[i] = Wr[i];
    __syncthreads();
    int warp = threadIdx.x >> 5, j = threadIdx.x & 31;
    int node = blockIdx.x * 8 + warp;
    if (node >= n) return;
    int base = off[node], end = off[node + 1];
    int deg = end - base;
    float a0 = 0.f, a1 = 0.f, a2 = 0.f, a3 = 0.f;
    float s0 = 0.f, s1 = 0.f, s2 = 0.f, s3 = 0.f;
    for (int i = base; i < end; i += 32) {
        int nbr = (i + j < end) ? adj[i + j] : 0;
        int m = min(32, end - i);
        int k = 0;
        for (; k + 4 <= m; k += 4) {
            int n0 = __shfl_sync(0xffffffffu, nbr, k);
            int n1 = __shfl_sync(0xffffffffu, nbr, k + 1);
            int n2 = __shfl_sync(0xffffffffu, nbr, k + 2);
            int n3 = __shfl_sync(0xffffffffu, nbr, k + 3);
            a0 += y[(size_t)n0 * D_H + j];  s0 += __ldg(gc + n0);
            a1 += y[(size_t)n1 * D_H + j];  s1 += __ldg(gc + n1);
            a2 += y[(size_t)n2 * D_H + j];  s2 += __ldg(gc + n2);
            a3 += y[(size_t)n3 * D_H + j];  s3 += __ldg(gc + n3);
        }
        for (; k < m; ++k) {
            int nk = __shfl_sync(0xffffffffu, nbr, k);
            a0 += y[(size_t)nk * D_H + j];
            s0 += __ldg(gc + nk);
        }
    }
    float inv = 1.0f / fmaxf((float)deg, 1.0f);
    float mean = (a0 + a1 + a2 + a3) * inv;
    float mean_gc = (s0 + s1 + s2 + s3) * inv;
    float xa = x[(size_t)node * D_IN + j];
    float xb = x[(size_t)node * D_IN + 32 + j];
    float lin = b[j];
    #pragma unroll
    for (int k = 0; k < 32; ++k)
        lin += __shfl_sync(0xffffffffu, xa, k) * sW[k * D_H + j];
    #pragma unroll
    for (int k = 0; k < 32; ++k)
        lin += __shfl_sync(0xffffffffu, xb, k) * sW[(k + 32) * D_H + j];
    float h = fmaxf(mean + lin, 0.0f);
    float v = h * weff[j];
    #pragma unroll
    for (int o = 16; o; o >>= 1) v += __shfl_xor_sync(0xffffffffu, v, o);
    if (j == 0) {
        float logit = mean_gc + v + g_bias_eff[0];
        out[node] = 1.0f / (1.0f + expf(-logit));
    }
}

// ---------------- launch ----------------------------------------------------

extern "C" void kernel_launch(void* const* d_in, const int* in_sizes, int n_in,
                              void* d_out, int out_size) {
    const float* x_customer = (const float*)d_in[0];
    const float* x_product  = (const float*)d_in[1];
    const int*   edge_c2p   = (const int*)d_in[2];
    const int*   edge_p2c   = (const int*)d_in[3];
    const float* W1l_r1 = (const float*)d_in[4];
    const float* b1_r1  = (const float*)d_in[5];
    const float* W1r_r1 = (const float*)d_in[6];
    const float* W1l_r2 = (const float*)d_in[7];
    const float* b1_r2  = (const float*)d_in[8];
    const float* W1r_r2 = (const float*)d_in[9];
    const float* W2l_r1 = (const float*)d_in[10];
    const float* b2_r1  = (const float*)d_in[11];
    const float* W2r_r1 = (const float*)d_in[12];
    const float* Wlin   = (const float*)d_in[16];
    const float* blin   = (const float*)d_in[17];
    float* out = (float*)d_out;

    const int N = N_NODES;
    const int E = in_sizes[2] / 2;

    float *p_ycp, *p_ypc, *p_gc, *p_w2l, *p_w2r;
    int *p_off_p, *p_off_c, *p_cur_p, *p_cur_c, *p_adj_p, *p_adj_c;
    cudaGetSymbolAddress((void**)&p_ycp,  g_ycp);
    cudaGetSymbolAddress((void**)&p_ypc,  g_ypc);
    cudaGetSymbolAddress((void**)&p_gc,   g_gc);
    cudaGetSymbolAddress((void**)&p_w2l,  g_w2l_eff);
    cudaGetSymbolAddress((void**)&p_w2r,  g_w2r_eff);
    cudaGetSymbolAddress((void**)&p_off_p, g_off_p);
    cudaGetSymbolAddress((void**)&p_off_c, g_off_c);
    cudaGetSymbolAddress((void**)&p_cur_p, g_cur_p);
    cudaGetSymbolAddress((void**)&p_cur_c, g_cur_c);
    cudaGetSymbolAddress((void**)&p_adj_p, g_adj_p);
    cudaGetSymbolAddress((void**)&p_adj_c, g_adj_c);

    const int TB = 256;
    int nodeBlocks = (N + TB - 1) / TB;
    int edgeBlocks = (E + TB - 1) / TB;
    int warpBlocks = (N + 7) / 8;

    // effective layer2 + head weights
    k_eff<<<1, 32>>>(W2l_r1, W2r_r1, b2_r1, Wlin, blin);

    // dense projections
    k_proj<<<warpBlocks, TB>>>(x_customer, W1l_r1, p_ycp, N);
    k_proj<<<warpBlocks, TB>>>(x_product,  W1l_r2, p_ypc, N);

    // CSR build: c2p (dst=product) and p2c (dst=customer)
    k_zero_i<<<nodeBlocks, TB>>>(p_cur_p, N);
    k_zero_i<<<nodeBlocks, TB>>>(p_cur_c, N);
    k_count<<<edgeBlocks, TB>>>(edge_c2p, p_cur_p, E);
    k_count<<<edgeBlocks, TB>>>(edge_p2c, p_cur_c, E);
    k_scan<<<1, 1024>>>(p_cur_p, p_off_p, p_cur_p, N);  // cur doubles as cnt then cursor
    k_scan<<<1, 1024>>>(p_cur_c, p_off_c, p_cur_c, N);
    k_fill<<<edgeBlocks, TB>>>(edge_c2p, p_cur_p, p_adj_p, E);
    k_fill<<<edgeBlocks, TB>>>(edge_p2c, p_cur_c, p_adj_c, E);

    // customer gather -> scalar g_c
    k_gather_c<<<warpBlocks, TB>>>(x_customer, W1r_r2, b1_r2, p_ypc,
                                   p_off_c, p_adj_c, p_w2l, p_gc, N);
    // product gather -> sigmoid output (fuses layer1 agg, layer2 agg, head)
    k_gather_p<<<warpBlocks, TB>>>(x_product, W1r_r1, b1_r1, p_ycp,
                                   p_off_p, p_adj_p, p_w2r, p_gc, out, N);
}

// round 3
// speedup vs baseline: 1.8893x; 1.8893x over previous
#include <cuda_runtime.h>
#include <cuda_bf16.h>
#include <math.h>

#define N_NODES 100000
#define D_IN    64
#define D_H     32
#define TOTAL_H (N_NODES * D_H)

// ---------------- scratch (device globals) ----------------------------------
__device__ float g_aggp[TOTAL_H];     // layer1 agg into products
__device__ float g_aggc[TOTAL_H];     // layer1 agg into customers
__device__ float g_ycp [TOTAL_H];     // x_customer @ W1l_r1
__device__ float g_ypc [TOTAL_H];     // x_product  @ W1l_r2
__device__ float g_cntp[N_NODES];
__device__ float g_cntc[N_NODES];
__device__ float g_gc  [N_NODES];     // per-customer folded scalar
__device__ float g_aggs[N_NODES];     // layer2 scalar agg into products
__device__ float g_w2l_eff[D_H];
__device__ float g_w2r_eff[D_H];
__device__ float g_bias_eff[1];

// ---------------- kernels ---------------------------------------------------

// Zero every accumulator in one pass (float4 stores).
__global__ void k_zero_all() {
    int i = blockIdx.x * blockDim.x + threadIdx.x;
    int stride = gridDim.x * blockDim.x;
    float4 z = make_float4(0.f, 0.f, 0.f, 0.f);
    for (int k = i; k < TOTAL_H / 4; k += stride) {
        reinterpret_cast<float4*>(g_aggp)[k] = z;
        reinterpret_cast<float4*>(g_aggc)[k] = z;
    }
    for (int k = i; k < N_NODES / 4; k += stride) {
        reinterpret_cast<float4*>(g_cntp)[k] = z;
        reinterpret_cast<float4*>(g_cntc)[k] = z;
        reinterpret_cast<float4*>(g_aggs)[k] = z;
    }
}

// Effective layer2+head weights: w_eff[i] = sum_j W2[i][j] * Wlin[j]
__global__ void k_eff(const float* __restrict__ W2l, const float* __restrict__ W2r,
                      const float* __restrict__ b2, const float* __restrict__ Wlin,
                      const float* __restrict__ blin) {
    int i = threadIdx.x;  // 0..31
    float wl = 0.f, wr = 0.f;
    #pragma unroll
    for (int j = 0; j < D_H; ++j) {
        float wj = Wlin[j];
        wl += W2l[i * D_H + j] * wj;
        wr += W2r[i * D_H + j] * wj;
    }
    g_w2l_eff[i] = wl;
    g_w2r_eff[i] = wr;
    float bv = b2[i] * Wlin[i];
    #pragma unroll
    for (int o = 16; o; o >>= 1) bv += __shfl_xor_sync(0xffffffffu, bv, o);
    if (i == 0) g_bias_eff[0] = bv + blin[0];
}

// y[n,32] = x[n,64] @ W[64,32]. Grid-stride, warp per node; W loaded once/block.
__global__ void k_proj(const float* __restrict__ x, const float* __restrict__ W,
                       float* __restrict__ y, int n) {
    __shared__ float sW[D_IN * D_H];
    for (int i = threadIdx.x; i < D_IN * D_H; i += blockDim.x) sW[i] = W[i];
    __syncthreads();
    int j = threadIdx.x & 31;
    int warpId = (blockIdx.x * blockDim.x + threadIdx.x) >> 5;
    int nWarps = (gridDim.x * blockDim.x) >> 5;
    for (int node = warpId; node < n; node += nWarps) {
        float xa = x[(size_t)node * D_IN + j];
        float xb = x[(size_t)node * D_IN + 32 + j];
        float acc = 0.f;
        #pragma unroll
        for (int k = 0; k < 32; ++k)
            acc += __shfl_sync(0xffffffffu, xa, k) * sW[k * D_H + j];
        #pragma unroll
        for (int k = 0; k < 32; ++k)
            acc += __shfl_sync(0xffffffffu, xb, k) * sW[(k + 32) * D_H + j];
        y[(size_t)node * D_H + j] = acc;
    }
}

// Per-edge scatter of 32-float rows + degree count. 8 threads/edge (float4).
__global__ void k_scatter32(const int* __restrict__ edge, const float* __restrict__ feat,
                            float* __restrict__ agg, float* __restrict__ cnt, int E) {
    long long t = (long long)blockIdx.x * blockDim.x + threadIdx.x;
    int e    = (int)(t >> 3);
    int lane = (int)(t & 7);
    if (e >= E) return;
    int s = __ldg(&edge[e]);
    int d = __ldg(&edge[E + e]);
    float4 v = *reinterpret_cast<const float4*>(feat + (size_t)s * D_H + lane * 4);
    atomicAdd(reinterpret_cast<float4*>(agg + (size_t)d * D_H + lane * 4), v);
    if (lane == 0) atomicAdd(cnt + d, 1.0f);
}

// Same, fused with the layer-2 scalar scatter: aggs[d] += gsrc[s].
__global__ void k_scatter32_fused(const int* __restrict__ edge, const float* __restrict__ feat,
                                  float* __restrict__ agg, float* __restrict__ cnt,
                                  const float* __restrict__ gsrc, float* __restrict__ aggs,
                                  int E) {
    long long t = (long long)blockIdx.x * blockDim.x + threadIdx.x;
    int e    = (int)(t >> 3);
    int lane = (int)(t & 7);
    if (e >= E) return;
    int s = __ldg(&edge[e]);
    int d = __ldg(&edge[E + e]);
    float4 v = *reinterpret_cast<const float4*>(feat + (size_t)s * D_H + lane * 4);
    atomicAdd(reinterpret_cast<float4*>(agg + (size_t)d * D_H + lane * 4), v);
    if (lane == 0) atomicAdd(cnt + d, 1.0f);
    if (lane == 1) atomicAdd(aggs + d, __ldg(gsrc + s));
}

// Customer nodes: h = relu(agg/max(cnt,1) + b + x@Wr); g = dot(h, weff).
// Grid-stride, warp per node; W loaded once/block.
__global__ void k_node_c(const float* __restrict__ x, const float* __restrict__ Wr,
                         const float* __restrict__ b, const float* __restrict__ agg,
                         const float* __restrict__ cnt, const float* __restrict__ weff,
                         float* __restrict__ g, int n) {
    __shared__ float sW[D_IN * D_H];
    for (int i = threadIdx.x; i < D_IN * D_H; i += blockDim.x) sW[i] = Wr[i];
    __syncthreads();
    int j = threadIdx.x & 31;
    int warpId = (blockIdx.x * blockDim.x + threadIdx.x) >> 5;
    int nWarps = (gridDim.x * blockDim.x) >> 5;
    float wj = weff[j];
    float bj = b[j];
    for (int node = warpId; node < n; node += nWarps) {
        float xa = x[(size_t)node * D_IN + j];
        float xb = x[(size_t)node * D_IN + 32 + j];
        float lin = bj;
        #pragma unroll
        for (int k = 0; k < 32; ++k)
            lin += __shfl_sync(0xffffffffu, xa, k) * sW[k * D_H + j];
        #pragma unroll
        for (int k = 0; k < 32; ++k)
            lin += __shfl_sync(0xffffffffu, xb, k) * sW[(k + 32) * D_H + j];
        float c = cnt[node];
        float h = fmaxf(lin + agg[(size_t)node * D_H + j] / fmaxf(c, 1.0f), 0.f);
        float v = h * wj;
        #pragma unroll
        for (int o = 16; o; o >>= 1) v += __shfl_xor_sync(0xffffffffu, v, o);
        if (j == 0) g[node] = v;
    }
}

// Product nodes: same + layer2 mean + sigmoid -> out.
__global__ void k_node_p_final(const float* __restrict__ x, const float* __restrict__ Wr,
                               const float* __restrict__ b, const float* __restrict__ agg,
                               const float* __restrict__ cnt, const float* __restrict__ weff,
                               const float* __restrict__ aggs, float* __restrict__ out, int n) {
    __shared__ float sW[D_IN * D_H];
    for (int i = threadIdx.x; i < D_IN * D_H; i += blockDim.x) sW[i] = Wr[i];
    __syncthreads();
    int j = threadIdx.x & 31;
    int warpId = (blockIdx.x * blockDim.x + threadIdx.x) >> 5;
    int nWarps = (gridDim.x * blockDim.x) >> 5;
    float wj = weff[j];
    float bj = b[j];
    float beff = g_bias_eff[0];
    for (int node = warpId; node < n; node += nWarps) {
        float xa = x[(size_t)node * D_IN + j];
        float xb = x[(size_t)node * D_IN + 32 + j];
        float lin = bj;
        #pragma unroll
        for (int k = 0; k < 32; ++k)
            lin += __shfl_sync(0xffffffffu, xa, k) * sW[k * D_H + j];
        #pragma unroll
        for (int k = 0; k < 32; ++k)
            lin += __shfl_sync(0xffffffffu, xb, k) * sW[(k + 32) * D_H + j];
        float c = fmaxf(cnt[node], 1.0f);
        float inv = 1.0f / c;
        float h = fmaxf(lin + agg[(size_t)node * D_H + j] * inv, 0.f);
        float v = h * wj;
        #pragma unroll
        for (int o = 16; o; o >>= 1) v += __shfl_xor_sync(0xffffffffu, v, o);
        if (j == 0) {
            float logit = aggs[node] * inv + v + beff;
            out[node] = 1.0f / (1.0f + expf(-logit));
        }
    }
}

// ---------------- launch ----------------------------------------------------

extern "C" void kernel_launch(void* const* d_in, const int* in_sizes, int n_in,
                              void* d_out, int out_size) {
    const float* x_customer = (const float*)d_in[0];
    const float* x_product  = (const float*)d_in[1];
    const int*   edge_c2p   = (const int*)d_in[2];
    const int*   edge_p2c   = (const int*)d_in[3];
    const float* W1l_r1 = (const float*)d_in[4];
    const float* b1_r1  = (const float*)d_in[5];
    const float* W1r_r1 = (const float*)d_in[6];
    const float* W1l_r2 = (const float*)d_in[7];
    const float* b1_r2  = (const float*)d_in[8];
    const float* W1r_r2 = (const float*)d_in[9];
    const float* W2l_r1 = (const float*)d_in[10];
    const float* b2_r1  = (const float*)d_in[11];
    const float* W2r_r1 = (const float*)d_in[12];
    const float* Wlin   = (const float*)d_in[16];
    const float* blin   = (const float*)d_in[17];
    float* out = (float*)d_out;

    const int N = N_NODES;
    const int E = in_sizes[2] / 2;

    float *p_aggp, *p_aggc, *p_ycp, *p_ypc, *p_cntp, *p_cntc, *p_gc, *p_aggs;
    float *p_w2l, *p_w2r;
    cudaGetSymbolAddress((void**)&p_aggp, g_aggp);
    cudaGetSymbolAddress((void**)&p_aggc, g_aggc);
    cudaGetSymbolAddress((void**)&p_ycp,  g_ycp);
    cudaGetSymbolAddress((void**)&p_ypc,  g_ypc);
    cudaGetSymbolAddress((void**)&p_cntp, g_cntp);
    cudaGetSymbolAddress((void**)&p_cntc, g_cntc);
    cudaGetSymbolAddress((void**)&p_gc,   g_gc);
    cudaGetSymbolAddress((void**)&p_aggs, g_aggs);
    cudaGetSymbolAddress((void**)&p_w2l,  g_w2l_eff);
    cudaGetSymbolAddress((void**)&p_w2r,  g_w2r_eff);

    const int TB = 256;
    const int GS_BLOCKS = 1480;   // grid-stride blocks for dense kernels

    // 0: zero all accumulators
    k_zero_all<<<1024, TB>>>();
    // 1: effective layer2 + head weights
    k_eff<<<1, 32>>>(W2l_r1, W2r_r1, b2_r1, Wlin, blin);
    // 2,3: dense projections
    k_proj<<<GS_BLOCKS, TB>>>(x_product,  W1l_r2, p_ypc, N);
    k_proj<<<GS_BLOCKS, TB>>>(x_customer, W1l_r1, p_ycp, N);
    // 4: p2c scatter (profiled launch)
    long long scatThreads = (long long)E * 8;
    int scatBlocks = (int)((scatThreads + TB - 1) / TB);
    k_scatter32<<<scatBlocks, TB>>>(edge_p2c, p_ypc, p_aggc, p_cntc, E);
    // 5: customer node transform -> g_c
    k_node_c<<<GS_BLOCKS, TB>>>(x_customer, W1r_r2, b1_r2, p_aggc, p_cntc, p_w2l, p_gc, N);
    // 6: c2p scatter, fused with layer-2 scalar scatter of g_c
    k_scatter32_fused<<<scatBlocks, TB>>>(edge_c2p, p_ycp, p_aggp, p_cntp, p_gc, p_aggs, E);
    // 7: product node transform + head + sigmoid
    k_node_p_final<<<GS_BLOCKS, TB>>>(x_product, W1r_r1, b1_r1, p_aggp, p_cntp, p_w2r,
                                      p_aggs, out, N);
}

// round 4
// speedup vs baseline: 2.0243x; 1.0715x over previous
#include <cuda_runtime.h>
#include <cuda_bf16.h>
#include <math.h>

#define N_NODES 100000
#define D_IN    64
#define D_H     32
#define TOTAL_H (N_NODES * D_H)

// ---------------- scratch (device globals) ----------------------------------
__device__ float g_aggp[TOTAL_H];     // layer1 agg into products
__device__ float g_aggc[TOTAL_H];     // layer1 agg into customers
__device__ float g_ycp [TOTAL_H];     // x_customer @ W1l_r1
__device__ float g_ypc [TOTAL_H];     // x_product  @ W1l_r2
__device__ float g_linc[TOTAL_H];     // x_customer @ W1r_r2 + b1_r2
__device__ float g_linp[TOTAL_H];     // x_product  @ W1r_r1 + b1_r1
__device__ float g_cntp[N_NODES];
__device__ float g_cntc[N_NODES];
__device__ float g_gc  [N_NODES];     // per-customer folded scalar
__device__ float g_aggs[N_NODES];     // layer2 scalar agg into products
__device__ float g_w2l_eff[D_H];
__device__ float g_w2r_eff[D_H];
__device__ float g_bias_eff[1];

// ---------------- kernels ---------------------------------------------------

__global__ void k_zero_agg() {
    int i = blockIdx.x * blockDim.x + threadIdx.x;
    int stride = gridDim.x * blockDim.x;
    float4 z = make_float4(0.f, 0.f, 0.f, 0.f);
    for (int k = i; k < TOTAL_H / 4; k += stride) {
        reinterpret_cast<float4*>(g_aggp)[k] = z;
        reinterpret_cast<float4*>(g_aggc)[k] = z;
    }
}

__global__ void k_zero_cnt() {
    int i = blockIdx.x * blockDim.x + threadIdx.x;
    int stride = gridDim.x * blockDim.x;
    float4 z = make_float4(0.f, 0.f, 0.f, 0.f);
    for (int k = i; k < N_NODES / 4; k += stride) {
        reinterpret_cast<float4*>(g_cntp)[k] = z;
        reinterpret_cast<float4*>(g_cntc)[k] = z;
        reinterpret_cast<float4*>(g_aggs)[k] = z;
    }
}

// Effective layer2+head weights: w_eff[i] = sum_j W2[i][j] * Wlin[j]
__global__ void k_eff(const float* __restrict__ W2l, const float* __restrict__ W2r,
                      const float* __restrict__ b2, const float* __restrict__ Wlin,
                      const float* __restrict__ blin) {
    int i = threadIdx.x;  // 0..31
    float wl = 0.f, wr = 0.f;
    #pragma unroll
    for (int j = 0; j < D_H; ++j) {
        float wj = Wlin[j];
        wl += W2l[i * D_H + j] * wj;
        wr += W2r[i * D_H + j] * wj;
    }
    g_w2l_eff[i] = wl;
    g_w2r_eff[i] = wr;
    float bv = b2[i] * Wlin[i];
    #pragma unroll
    for (int o = 16; o; o >>= 1) bv += __shfl_xor_sync(0xffffffffu, bv, o);
    if (i == 0) g_bias_eff[0] = bv + blin[0];
}

// Dual matvec sharing one x-broadcast:
//   y[node]   = x[node] @ Wl
//   lin[node] = x[node] @ Wr + b
// Warp per node, grid-stride. 64 SHFL + 128 FFMA per node.
__global__ void k_prep(const float* __restrict__ x,
                       const float* __restrict__ Wl, const float* __restrict__ Wr,
                       const float* __restrict__ b,
                       float* __restrict__ y, float* __restrict__ lin, int n) {
    __shared__ float sWl[D_IN * D_H];
    __shared__ float sWr[D_IN * D_H];
    for (int i = threadIdx.x; i < D_IN * D_H; i += blockDim.x) {
        sWl[i] = Wl[i];
        sWr[i] = Wr[i];
    }
    __syncthreads();
    int j = threadIdx.x & 31;
    int warpId = (blockIdx.x * blockDim.x + threadIdx.x) >> 5;
    int nWarps = (gridDim.x * blockDim.x) >> 5;
    float bj = b[j];
    for (int node = warpId; node < n; node += nWarps) {
        float xa = x[(size_t)node * D_IN + j];
        float xb = x[(size_t)node * D_IN + 32 + j];
        float accl = 0.f;
        float accr = bj;
        #pragma unroll
        for (int k = 0; k < 32; ++k) {
            float xk = __shfl_sync(0xffffffffu, xa, k);
            accl += xk * sWl[k * D_H + j];
            accr += xk * sWr[k * D_H + j];
        }
        #pragma unroll
        for (int k = 0; k < 32; ++k) {
            float xk = __shfl_sync(0xffffffffu, xb, k);
            accl += xk * sWl[(k + 32) * D_H + j];
            accr += xk * sWr[(k + 32) * D_H + j];
        }
        y  [(size_t)node * D_H + j] = accl;
        lin[(size_t)node * D_H + j] = accr;
    }
}

// Per-edge scatter of 32-float rows + degree count. 8 threads/edge (float4).
__global__ void k_scatter32(const int* __restrict__ edge, const float* __restrict__ feat,
                            float* __restrict__ agg, float* __restrict__ cnt, int E) {
    long long t = (long long)blockIdx.x * blockDim.x + threadIdx.x;
    int e    = (int)(t >> 3);
    int lane = (int)(t & 7);
    if (e >= E) return;
    int s = __ldg(&edge[e]);
    int d = __ldg(&edge[E + e]);
    float4 v = *reinterpret_cast<const float4*>(feat + (size_t)s * D_H + lane * 4);
    atomicAdd(reinterpret_cast<float4*>(agg + (size_t)d * D_H + lane * 4), v);
    if (lane == 0) atomicAdd(cnt + d, 1.0f);
}

// Same, fused with the layer-2 scalar scatter: aggs[d] += gsrc[s].
__global__ void k_scatter32_fused(const int* __restrict__ edge, const float* __restrict__ feat,
                                  float* __restrict__ agg, float* __restrict__ cnt,
                                  const float* __restrict__ gsrc, float* __restrict__ aggs,
                                  int E) {
    long long t = (long long)blockIdx.x * blockDim.x + threadIdx.x;
    int e    = (int)(t >> 3);
    int lane = (int)(t & 7);
    if (e >= E) return;
    int s = __ldg(&edge[e]);
    int d = __ldg(&edge[E + e]);
    float4 v = *reinterpret_cast<const float4*>(feat + (size_t)s * D_H + lane * 4);
    atomicAdd(reinterpret_cast<float4*>(agg + (size_t)d * D_H + lane * 4), v);
    if (lane == 0) atomicAdd(cnt + d, 1.0f);
    if (lane == 1) atomicAdd(aggs + d, __ldg(gsrc + s));
}

// Customer post: h = relu(agg/max(cnt,1) + lin); g = dot(h, weff). Warp/node.
__global__ void k_post_c(const float* __restrict__ agg, const float* __restrict__ cnt,
                         const float* __restrict__ lin, const float* __restrict__ weff,
                         float* __restrict__ g, int n) {
    int j = threadIdx.x & 31;
    int warpId = (blockIdx.x * blockDim.x + threadIdx.x) >> 5;
    int nWarps = (gridDim.x * blockDim.x) >> 5;
    float wj = weff[j];
    for (int node = warpId; node < n; node += nWarps) {
        float inv = 1.0f / fmaxf(cnt[node], 1.0f);
        float h = fmaxf(agg[(size_t)node * D_H + j] * inv + lin[(size_t)node * D_H + j], 0.f);
        float v = h * wj;
        #pragma unroll
        for (int o = 16; o; o >>= 1) v += __shfl_xor_sync(0xffffffffu, v, o);
        if (j == 0) g[node] = v;
    }
}

// Product post: + layer2 mean + sigmoid -> out.
__global__ void k_post_p(const float* __restrict__ agg, const float* __restrict__ cnt,
                         const float* __restrict__ lin, const float* __restrict__ weff,
                         const float* __restrict__ aggs, float* __restrict__ out, int n) {
    int j = threadIdx.x & 31;
    int warpId = (blockIdx.x * blockDim.x + threadIdx.x) >> 5;
    int nWarps = (gridDim.x * blockDim.x) >> 5;
    float wj = weff[j];
    float beff = g_bias_eff[0];
    for (int node = warpId; node < n; node += nWarps) {
        float inv = 1.0f / fmaxf(cnt[node], 1.0f);
        float h = fmaxf(agg[(size_t)node * D_H + j] * inv + lin[(size_t)node * D_H + j], 0.f);
        float v = h * wj;
        #pragma unroll
        for (int o = 16; o; o >>= 1) v += __shfl_xor_sync(0xffffffffu, v, o);
        if (j == 0) {
            float logit = aggs[node] * inv + v + beff;
            out[node] = 1.0f / (1.0f + expf(-logit));
        }
    }
}

// ---------------- launch ----------------------------------------------------

extern "C" void kernel_launch(void* const* d_in, const int* in_sizes, int n_in,
                              void* d_out, int out_size) {
    const float* x_customer = (const float*)d_in[0];
    const float* x_product  = (const float*)d_in[1];
    const int*   edge_c2p   = (const int*)d_in[2];
    const int*   edge_p2c   = (const int*)d_in[3];
    const float* W1l_r1 = (const float*)d_in[4];
    const float* b1_r1  = (const float*)d_in[5];
    const float* W1r_r1 = (const float*)d_in[6];
    const float* W1l_r2 = (const float*)d_in[7];
    const float* b1_r2  = (const float*)d_in[8];
    const float* W1r_r2 = (const float*)d_in[9];
    const float* W2l_r1 = (const float*)d_in[10];
    const float* b2_r1  = (const float*)d_in[11];
    const float* W2r_r1 = (const float*)d_in[12];
    const float* Wlin   = (const float*)d_in[16];
    const float* blin   = (const float*)d_in[17];
    float* out = (float*)d_out;

    const int N = N_NODES;
    const int E = in_sizes[2] / 2;

    float *p_aggp, *p_aggc, *p_ycp, *p_ypc, *p_linc, *p_linp;
    float *p_cntp, *p_cntc, *p_gc, *p_aggs, *p_w2l, *p_w2r;
    cudaGetSymbolAddress((void**)&p_aggp, g_aggp);
    cudaGetSymbolAddress((void**)&p_aggc, g_aggc);
    cudaGetSymbolAddress((void**)&p_ycp,  g_ycp);
    cudaGetSymbolAddress((void**)&p_ypc,  g_ypc);
    cudaGetSymbolAddress((void**)&p_linc, g_linc);
    cudaGetSymbolAddress((void**)&p_linp, g_linp);
    cudaGetSymbolAddress((void**)&p_cntp, g_cntp);
    cudaGetSymbolAddress((void**)&p_cntc, g_cntc);
    cudaGetSymbolAddress((void**)&p_gc,   g_gc);
    cudaGetSymbolAddress((void**)&p_aggs, g_aggs);
    cudaGetSymbolAddress((void**)&p_w2l,  g_w2l_eff);
    cudaGetSymbolAddress((void**)&p_w2r,  g_w2r_eff);

    const int TB = 256;
    const int GS_BLOCKS = 1480;

    long long scatThreads = (long long)E * 8;
    int scatBlocks = (int)((scatThreads + TB - 1) / TB);

    // 0,1: zero accumulators
    k_zero_agg<<<1024, TB>>>();
    k_zero_cnt<<<256, TB>>>();
    // 2: effective layer2 + head weights
    k_eff<<<1, 32>>>(W2l_r1, W2r_r1, b2_r1, Wlin, blin);
    // 3: product prep  (y_pc = x_p@W1l_r2, lin_p = x_p@W1r_r1 + b1_r1)
    k_prep<<<GS_BLOCKS, TB>>>(x_product, W1l_r2, W1r_r1, b1_r1, p_ypc, p_linp, N);
    // 4: customer prep (y_cp = x_c@W1l_r1, lin_c = x_c@W1r_r2 + b1_r2)
    k_prep<<<GS_BLOCKS, TB>>>(x_customer, W1l_r1, W1r_r2, b1_r2, p_ycp, p_linc, N);
    // 5: p2c scatter (target of ncu -s 5)
    k_scatter32<<<scatBlocks, TB>>>(edge_p2c, p_ypc, p_aggc, p_cntc, E);
    // 6: customer post -> g_c
    k_post_c<<<GS_BLOCKS, TB>>>(p_aggc, p_cntc, p_linc, p_w2l, p_gc, N);
    // 7: c2p scatter fused with layer-2 scalar scatter
    k_scatter32_fused<<<scatBlocks, TB>>>(edge_c2p, p_ycp, p_aggp, p_cntp, p_gc, p_aggs, E);
    // 8: product post + head + sigmoid
    k_post_p<<<GS_BLOCKS, TB>>>(p_aggp, p_cntp, p_linp, p_w2r, p_aggs, out, N);
}

// round 5
// speedup vs baseline: 2.5157x; 1.2428x over previous
#include <cuda_runtime.h>
#include <cuda_bf16.h>
#include <math.h>

#define N_NODES 100000
#define D_IN    64
#define D_H     32
#define TOTAL_H (N_NODES * D_H)

// ---------------- scratch (device globals, 16B aligned for float4) ----------
__device__ __align__(16) float g_aggp[TOTAL_H];
__device__ __align__(16) float g_aggc[TOTAL_H];
__device__ __align__(16) float g_ycp [TOTAL_H];
__device__ __align__(16) float g_ypc [TOTAL_H];
__device__ __align__(16) float g_linc[TOTAL_H];
__device__ __align__(16) float g_linp[TOTAL_H];
__device__ __align__(16) float g_cntp[N_NODES];
__device__ __align__(16) float g_cntc[N_NODES];
__device__ __align__(16) float g_gc  [N_NODES];
__device__ __align__(16) float g_aggs[N_NODES];
__device__ float g_w2l_eff[D_H];
__device__ float g_w2r_eff[D_H];
__device__ float g_bias_eff[1];

// ---------------- kernels ---------------------------------------------------

__global__ void k_zero_agg() {
    int i = blockIdx.x * blockDim.x + threadIdx.x;
    int stride = gridDim.x * blockDim.x;
    float4 z = make_float4(0.f, 0.f, 0.f, 0.f);
    for (int k = i; k < TOTAL_H / 4; k += stride) {
        reinterpret_cast<float4*>(g_aggp)[k] = z;
        reinterpret_cast<float4*>(g_aggc)[k] = z;
    }
}

__global__ void k_zero_cnt() {
    int i = blockIdx.x * blockDim.x + threadIdx.x;
    int stride = gridDim.x * blockDim.x;
    float4 z = make_float4(0.f, 0.f, 0.f, 0.f);
    for (int k = i; k < N_NODES / 4; k += stride) {
        reinterpret_cast<float4*>(g_cntp)[k] = z;
        reinterpret_cast<float4*>(g_cntc)[k] = z;
        reinterpret_cast<float4*>(g_aggs)[k] = z;
    }
}

__global__ void k_eff(const float* __restrict__ W2l, const float* __restrict__ W2r,
                      const float* __restrict__ b2, const float* __restrict__ Wlin,
                      const float* __restrict__ blin) {
    int i = threadIdx.x;  // 0..31
    float wl = 0.f, wr = 0.f;
    #pragma unroll
    for (int j = 0; j < D_H; ++j) {
        float wj = Wlin[j];
        wl += W2l[i * D_H + j] * wj;
        wr += W2r[i * D_H + j] * wj;
    }
    g_w2l_eff[i] = wl;
    g_w2r_eff[i] = wr;
    float bv = b2[i] * Wlin[i];
    #pragma unroll
    for (int o = 16; o; o >>= 1) bv += __shfl_xor_sync(0xffffffffu, bv, o);
    if (i == 0) g_bias_eff[0] = bv + blin[0];
}

// Dual matvec, 1 node per THREAD, register accumulators:
//   y[node]   = x[node] @ Wl
//   lin[node] = x[node] @ Wr + b
// Weights read as warp-uniform float4 broadcasts from shared (conflict-free).
__global__ void k_prep(const float* __restrict__ x,
                       const float* __restrict__ Wl, const float* __restrict__ Wr,
                       const float* __restrict__ b,
                       float* __restrict__ y, float* __restrict__ lin, int n) {
    __shared__ float4 sWl[D_IN * 8];   // [64][8] float4 = W row k, cols j4*4..+3
    __shared__ float4 sWr[D_IN * 8];
    __shared__ float  sb[D_H];
    for (int i = threadIdx.x; i < D_IN * 8; i += blockDim.x) {
        sWl[i] = reinterpret_cast<const float4*>(Wl)[i];
        sWr[i] = reinterpret_cast<const float4*>(Wr)[i];
    }
    if (threadIdx.x < D_H) sb[threadIdx.x] = b[threadIdx.x];
    __syncthreads();
    int node = blockIdx.x * blockDim.x + threadIdx.x;
    if (node >= n) return;

    float accl[D_H], accr[D_H];
    #pragma unroll
    for (int j = 0; j < D_H; ++j) { accl[j] = 0.f; accr[j] = 0.f; }

    const float4* x4 = reinterpret_cast<const float4*>(x + (size_t)node * D_IN);
    #pragma unroll 2
    for (int kc = 0; kc < D_IN / 4; ++kc) {
        float4 xv = __ldg(x4 + kc);
        #pragma unroll
        for (int d = 0; d < 4; ++d) {
            float xk = (d == 0) ? xv.x : (d == 1) ? xv.y : (d == 2) ? xv.z : xv.w;
            int k = kc * 4 + d;
            #pragma unroll
            for (int j4 = 0; j4 < 8; ++j4) {
                float4 wl = sWl[k * 8 + j4];
                float4 wr = sWr[k * 8 + j4];
                accl[j4*4+0] += xk * wl.x;  accl[j4*4+1] += xk * wl.y;
                accl[j4*4+2] += xk * wl.z;  accl[j4*4+3] += xk * wl.w;
                accr[j4*4+0] += xk * wr.x;  accr[j4*4+1] += xk * wr.y;
                accr[j4*4+2] += xk * wr.z;  accr[j4*4+3] += xk * wr.w;
            }
        }
    }
    float4* yo = reinterpret_cast<float4*>(y   + (size_t)node * D_H);
    float4* lo = reinterpret_cast<float4*>(lin + (size_t)node * D_H);
    #pragma unroll
    for (int j4 = 0; j4 < 8; ++j4) {
        yo[j4] = make_float4(accl[j4*4], accl[j4*4+1], accl[j4*4+2], accl[j4*4+3]);
        lo[j4] = make_float4(accr[j4*4+0] + sb[j4*4+0],
                             accr[j4*4+1] + sb[j4*4+1],
                             accr[j4*4+2] + sb[j4*4+2],
                             accr[j4*4+3] + sb[j4*4+3]);
    }
}

// Per-edge scatter of 32-float rows + degree count. 8 threads/edge (float4).
__global__ void k_scatter32(const int* __restrict__ edge, const float* __restrict__ feat,
                            float* __restrict__ agg, float* __restrict__ cnt, int E) {
    long long t = (long long)blockIdx.x * blockDim.x + threadIdx.x;
    int e    = (int)(t >> 3);
    int lane = (int)(t & 7);
    if (e >= E) return;
    int s = __ldg(&edge[e]);
    int d = __ldg(&edge[E + e]);
    float4 v = *reinterpret_cast<const float4*>(feat + (size_t)s * D_H + lane * 4);
    atomicAdd(reinterpret_cast<float4*>(agg + (size_t)d * D_H + lane * 4), v);
    if (lane == 0) atomicAdd(cnt + d, 1.0f);
}

// Same, fused with the layer-2 scalar scatter: aggs[d] += gsrc[s].
__global__ void k_scatter32_fused(const int* __restrict__ edge, const float* __restrict__ feat,
                                  float* __restrict__ agg, float* __restrict__ cnt,
                                  const float* __restrict__ gsrc, float* __restrict__ aggs,
                                  int E) {
    long long t = (long long)blockIdx.x * blockDim.x + threadIdx.x;
    int e    = (int)(t >> 3);
    int lane = (int)(t & 7);
    if (e >= E) return;
    int s = __ldg(&edge[e]);
    int d = __ldg(&edge[E + e]);
    float4 v = *reinterpret_cast<const float4*>(feat + (size_t)s * D_H + lane * 4);
    atomicAdd(reinterpret_cast<float4*>(agg + (size_t)d * D_H + lane * 4), v);
    if (lane == 0) atomicAdd(cnt + d, 1.0f);
    if (lane == 1) atomicAdd(aggs + d, __ldg(gsrc + s));
}

// Customer post: h = relu(agg/max(cnt,1) + lin); g = dot(h, weff). Warp/node.
__global__ void k_post_c(const float* __restrict__ agg, const float* __restrict__ cnt,
                         const float* __restrict__ lin, const float* __restrict__ weff,
                         float* __restrict__ g, int n) {
    int j = threadIdx.x & 31;
    int warpId = (blockIdx.x * blockDim.x + threadIdx.x) >> 5;
    int nWarps = (gridDim.x * blockDim.x) >> 5;
    float wj = weff[j];
    for (int node = warpId; node < n; node += nWarps) {
        float inv = 1.0f / fmaxf(cnt[node], 1.0f);
        float h = fmaxf(agg[(size_t)node * D_H + j] * inv + lin[(size_t)node * D_H + j], 0.f);
        float v = h * wj;
        #pragma unroll
        for (int o = 16; o; o >>= 1) v += __shfl_xor_sync(0xffffffffu, v, o);
        if (j == 0) g[node] = v;
    }
}

// Product post: + layer2 mean + sigmoid -> out.
__global__ void k_post_p(const float* __restrict__ agg, const float* __restrict__ cnt,
                         const float* __restrict__ lin, const float* __restrict__ weff,
                         const float* __restrict__ aggs, float* __restrict__ out, int n) {
    int j = threadIdx.x & 31;
    int warpId = (blockIdx.x * blockDim.x + threadIdx.x) >> 5;
    int nWarps = (gridDim.x * blockDim.x) >> 5;
    float wj = weff[j];
    float beff = g_bias_eff[0];
    for (int node = warpId; node < n; node += nWarps) {
        float inv = 1.0f / fmaxf(cnt[node], 1.0f);
        float h = fmaxf(agg[(size_t)node * D_H + j] * inv + lin[(size_t)node * D_H + j], 0.f);
        float v = h * wj;
        #pragma unroll
        for (int o = 16; o; o >>= 1) v += __shfl_xor_sync(0xffffffffu, v, o);
        if (j == 0) {
            float logit = aggs[node] * inv + v + beff;
            out[node] = 1.0f / (1.0f + expf(-logit));
        }
    }
}

// ---------------- launch ----------------------------------------------------

extern "C" void kernel_launch(void* const* d_in, const int* in_sizes, int n_in,
                              void* d_out, int out_size) {
    const float* x_customer = (const float*)d_in[0];
    const float* x_product  = (const float*)d_in[1];
    const int*   edge_c2p   = (const int*)d_in[2];
    const int*   edge_p2c   = (const int*)d_in[3];
    const float* W1l_r1 = (const float*)d_in[4];
    const float* b1_r1  = (const float*)d_in[5];
    const float* W1r_r1 = (const float*)d_in[6];
    const float* W1l_r2 = (const float*)d_in[7];
    const float* b1_r2  = (const float*)d_in[8];
    const float* W1r_r2 = (const float*)d_in[9];
    const float* W2l_r1 = (const float*)d_in[10];
    const float* b2_r1  = (const float*)d_in[11];
    const float* W2r_r1 = (const float*)d_in[12];
    const float* Wlin   = (const float*)d_in[16];
    const float* blin   = (const float*)d_in[17];
    float* out = (float*)d_out;

    const int N = N_NODES;
    const int E = in_sizes[2] / 2;

    float *p_aggp, *p_aggc, *p_ycp, *p_ypc, *p_linc, *p_linp;
    float *p_cntp, *p_cntc, *p_gc, *p_aggs, *p_w2l, *p_w2r;
    cudaGetSymbolAddress((void**)&p_aggp, g_aggp);
    cudaGetSymbolAddress((void**)&p_aggc, g_aggc);
    cudaGetSymbolAddress((void**)&p_ycp,  g_ycp);
    cudaGetSymbolAddress((void**)&p_ypc,  g_ypc);
    cudaGetSymbolAddress((void**)&p_linc, g_linc);
    cudaGetSymbolAddress((void**)&p_linp, g_linp);
    cudaGetSymbolAddress((void**)&p_cntp, g_cntp);
    cudaGetSymbolAddress((void**)&p_cntc, g_cntc);
    cudaGetSymbolAddress((void**)&p_gc,   g_gc);
    cudaGetSymbolAddress((void**)&p_aggs, g_aggs);
    cudaGetSymbolAddress((void**)&p_w2l,  g_w2l_eff);
    cudaGetSymbolAddress((void**)&p_w2r,  g_w2r_eff);

    const int TB = 256;
    const int GS_BLOCKS = 1480;
    int prepBlocks = (N + TB - 1) / TB;

    long long scatThreads = (long long)E * 8;
    int scatBlocks = (int)((scatThreads + TB - 1) / TB);

    // 0,1: zero accumulators
    k_zero_agg<<<1024, TB>>>();
    k_zero_cnt<<<256, TB>>>();
    // 2: effective layer2 + head weights
    k_eff<<<1, 32>>>(W2l_r1, W2r_r1, b2_r1, Wlin, blin);
    // 3: product prep  (y_pc = x_p@W1l_r2, lin_p = x_p@W1r_r1 + b1_r1)
    k_prep<<<prepBlocks, TB>>>(x_product, W1l_r2, W1r_r1, b1_r1, p_ypc, p_linp, N);
    // 4: customer prep (y_cp = x_c@W1l_r1, lin_c = x_c@W1r_r2 + b1_r2)
    k_prep<<<prepBlocks, TB>>>(x_customer, W1l_r1, W1r_r2, b1_r2, p_ycp, p_linc, N);
    // 5: p2c scatter (target of ncu -s 5)
    k_scatter32<<<scatBlocks, TB>>>(edge_p2c, p_ypc, p_aggc, p_cntc, E);
    // 6: customer post -> g_c
    k_post_c<<<GS_BLOCKS, TB>>>(p_aggc, p_cntc, p_linc, p_w2l, p_gc, N);
    // 7: c2p scatter fused with layer-2 scalar scatter
    k_scatter32_fused<<<scatBlocks, TB>>>(edge_c2p, p_ycp, p_aggp, p_cntp, p_gc, p_aggs, E);
    // 8: product post + head + sigmoid
    k_post_p<<<GS_BLOCKS, TB>>>(p_aggp, p_cntp, p_linp, p_w2r, p_aggs, out, N);
}